// round 8
// baseline (speedup 1.0000x reference)
#include <cuda_runtime.h>
#include <cuda_fp16.h>
#include <cuda_pipeline.h>

// Problem: DilatedAttention  q,k,v: [4, 8192, 16, 64] f32 -> out same shape.
// Groups: (g, r, segment, offset, hmin):
//   g0: (6, 1, 2048, 0, 0)   eligible pos: all,       heads 0..5
//   g1: (5, 2, 4096, 1, 5)   eligible pos: p%2==1,    heads 5..9
//   g2: (5, 4, 8192, 2, 10)  eligible pos: p%4==2,    heads 10..14
// head 15 never written (faithful to reference).
// Per eligible position: gxg attention over the HEAD axis (d=64), then
// x normalized by sum of x over all eligible positions per (b, head, d),
// scatter-added, divided by 3.

#define SEQ   8192
#define BATCH 4
#define HEADS 16
#define DIM   64

#define X0_BASE 0
#define X0_SIZE (BATCH*8192*6*DIM)
#define X1_BASE (X0_BASE + X0_SIZE)
#define X1_SIZE (BATCH*4096*5*DIM)
#define X2_BASE (X1_BASE + X1_SIZE)
#define X2_SIZE (BATCH*2048*5*DIM)
#define X_TOTAL (X2_BASE + X2_SIZE)

#define S0_BASE 0
#define S1_BASE (S0_BASE + BATCH*6*DIM)
#define S2_BASE (S1_BASE + BATCH*5*DIM)
#define S_TOTAL (S2_BASE + BATCH*5*DIM)     // 4096

// Dynamic smem: Q,K,V stage buffers (16 pos x G x 64 f32 each) + 8 warp sum
// slices (G*64 f32 each). Sized for G=6: (3*16*6*64 + 8*6*64) * 4 = 86016 B.
#define SMEM_BYTES ((3*16*6*64 + 8*6*64) * 4)

__device__ __half  g_xh[X_TOTAL];     // fp16 scratch for x
__device__ double  g_sums[S_TOTAL];   // zero-initialized; re-zeroed by pass2
__device__ float   g_rsums[S_TOTAL];

__global__ void rsums_kernel() {
    int i = blockIdx.x * blockDim.x + threadIdx.x;
    if (i < S_TOTAL) g_rsums[i] = (float)(1.0 / (3.0 * g_sums[i]));
}

// Issue async copies of one 16-position stage of Q and K into smem.
// Stage layout: [pos 0..15][head 0..G-1][dim 0..63] floats (f4 idx = linear).
template<int G, int R, int OFF, int HMIN, int PB>
__device__ __forceinline__ void stage_qk(
    float* Qb, float* Kb,
    const float* __restrict__ q, const float* __restrict__ k,
    int b, int jbase, int tid)
{
    #pragma unroll
    for (int u = 0; u < G; u++) {
        const int idx  = u * 256 + tid;        // float4 index, < G*256
        const int pos  = idx / (G * 16);       // compile-time const divisor
        const int rem  = idx - pos * (G * 16);
        const int head = rem >> 4;
        const int l    = rem & 15;
        const int jb   = (jbase + pos) - b * PB;
        const int p    = jb * R + OFF;
        const int off  = ((b * SEQ + p) * HEADS + HMIN + head) * DIM + l * 4;
        __pipeline_memcpy_async(Qb + idx * 4, q + off, 16);
        __pipeline_memcpy_async(Kb + idx * 4, k + off, 16);
    }
}

template<int G, int R, int OFF, int HMIN, int PB>
__device__ __forceinline__ void stage_v(
    float* Vb, const float* __restrict__ v,
    int b, int jbase, int tid)
{
    #pragma unroll
    for (int u = 0; u < G; u++) {
        const int idx  = u * 256 + tid;
        const int pos  = idx / (G * 16);
        const int rem  = idx - pos * (G * 16);
        const int head = rem >> 4;
        const int l    = rem & 15;
        const int jb   = (jbase + pos) - b * PB;
        const int p    = jb * R + OFF;
        const int off  = ((b * SEQ + p) * HEADS + HMIN + head) * DIM + l * 4;
        __pipeline_memcpy_async(Vb + idx * 4, v + off, 16);
    }
}

// Pass-1 body: one block = 64 eligible positions (4 stages of 16 positions,
// 8 warps x 2 halves). Lane layout: 16 lanes per position, lane lh owns dims
// [4*lh, 4*lh+4). Q/K/V staged through smem via cp.async, prefetched one
// stage ahead: QK(i+1) issued after scores(i) (covered by butterfly/softmax/
// AV), V(i+1) issued after AV(i) (covered by next stage's scores/softmax).
// Commit groups stay symmetric (empty commits on last stage) so wait_prior(1)
// is always the right wait. Sums: per-warp private smem slice, block-reduced
// once in double -> one double atomic per element.
template<int G, int R, int OFF, int HMIN, int PB, int XBASE, int SUMBASE>
__device__ __forceinline__ void pass1_body(
    int blockOffset, float* sm,
    const float* __restrict__ q,
    const float* __restrict__ k,
    const float* __restrict__ v)
{
    const int tid  = threadIdx.x;
    const int w    = tid >> 5;
    const int lane = tid & 31;
    const int half = lane >> 4;
    const int lh   = lane & 15;

    float* Qb   = sm;
    float* Kb   = sm + 1024 * G;      // 16*G*64
    float* Vb   = sm + 2048 * G;
    float* sblk = sm + 3072 * G;      // 8 slices of G*64

    const int blockBase = blockOffset * 64;   // eligible-position index (global)
    const int b = blockBase / PB;             // 64 divides PB; no batch straddle

    // Prologue: stage 0 in flight, then zero sum slices while copies fly.
    stage_qk<G, R, OFF, HMIN, PB>(Qb, Kb, q, k, b, blockBase, tid);
    __pipeline_commit();
    stage_v<G, R, OFF, HMIN, PB>(Vb, v, b, blockBase, tid);
    __pipeline_commit();

    for (int i = tid; i < 8 * G * 64; i += 256) sblk[i] = 0.0f;

    float* myslice = sblk + w * (G * 64);
    const int slot = w * 2 + half;            // position slot within stage

    #pragma unroll 1
    for (int it = 0; it < 4; it++) {
        // outstanding: [QK(it), V(it)] -> wait all but newest = QK(it) done
        __pipeline_wait_prior(1);
        __syncthreads();

        const int j = blockBase + it * 16 + slot;   // global eligible idx

        // Scores from smem: Q row resident in regs, K streamed per head.
        const float* Qrow = Qb + slot * (G * 64) + 4 * lh;
        const float* Krow = Kb + slot * (G * 64) + 4 * lh;

        float4 qv[G];
        #pragma unroll
        for (int a = 0; a < G; a++)
            qv[a] = *reinterpret_cast<const float4*>(Qrow + a * 64);

        float s[G][G];
        #pragma unroll
        for (int c = 0; c < G; c++) {
            const float4 kc = *reinterpret_cast<const float4*>(Krow + c * 64);
            #pragma unroll
            for (int a = 0; a < G; a++)
                s[a][c] = qv[a].x * kc.x + qv[a].y * kc.y
                        + qv[a].z * kc.z + qv[a].w * kc.w;
        }

        __syncthreads();   // all warps done reading Q/K buffers
        if (it < 3)
            stage_qk<G, R, OFF, HMIN, PB>(Qb, Kb, q, k, b, blockBase + (it + 1) * 16, tid);
        __pipeline_commit();   // empty group when it==3 keeps ring symmetric

        // Butterfly reduce within each 16-lane half.
        #pragma unroll
        for (int m = 1; m < 16; m <<= 1)
            #pragma unroll
            for (int a = 0; a < G; a++)
                #pragma unroll
                for (int c = 0; c < G; c++)
                    s[a][c] += __shfl_xor_sync(0xffffffffu, s[a][c], m);

        // Softmax per row (scale 0.125), weights left in s.
        #pragma unroll
        for (int a = 0; a < G; a++) {
            float mx = s[a][0];
            #pragma unroll
            for (int c = 1; c < G; c++) mx = fmaxf(mx, s[a][c]);
            float tot = 0.0f;
            #pragma unroll
            for (int c = 0; c < G; c++) {
                s[a][c] = __expf((s[a][c] - mx) * 0.125f);
                tot += s[a][c];
            }
            const float rinv = __fdividef(1.0f, tot);
            #pragma unroll
            for (int c = 0; c < G; c++) s[a][c] *= rinv;
        }

        // outstanding: [V(it), QK(it+1)/empty] -> wait all but newest = V(it)
        __pipeline_wait_prior(1);
        __syncthreads();

        // AV from smem V, emit fp16 x, accumulate sums into warp slice.
        const float* Vrow = Vb + slot * (G * 64) + 4 * lh;
        const int xbase = XBASE + (j * G) * DIM + 4 * lh;
        #pragma unroll
        for (int a = 0; a < G; a++) {
            float4 xo = make_float4(0.f, 0.f, 0.f, 0.f);
            #pragma unroll
            for (int c = 0; c < G; c++) {
                const float4 vc = *reinterpret_cast<const float4*>(Vrow + c * 64);
                xo.x += s[a][c] * vc.x; xo.y += s[a][c] * vc.y;
                xo.z += s[a][c] * vc.z; xo.w += s[a][c] * vc.w;
            }

            const __half2 h01 = __floats2half2_rn(xo.x, xo.y);
            const __half2 h23 = __floats2half2_rn(xo.z, xo.w);
            uint2 raw;
            raw.x = *reinterpret_cast<const unsigned int*>(&h01);
            raw.y = *reinterpret_cast<const unsigned int*>(&h23);
            *reinterpret_cast<uint2*>(g_xh + xbase + a * DIM) = raw;

            // Combine the two halves, add into this warp's slice
            // (half==0 lanes write distinct float4 slots -- race-free).
            xo.x += __shfl_down_sync(0xffffffffu, xo.x, 16);
            xo.y += __shfl_down_sync(0xffffffffu, xo.y, 16);
            xo.z += __shfl_down_sync(0xffffffffu, xo.z, 16);
            xo.w += __shfl_down_sync(0xffffffffu, xo.w, 16);
            if (half == 0) {
                float4* slotp = reinterpret_cast<float4*>(myslice + a * 64 + 4 * lh);
                float4 cur = *slotp;
                cur.x += xo.x; cur.y += xo.y;
                cur.z += xo.z; cur.w += xo.w;
                *slotp = cur;
            }
        }

        __syncthreads();   // all warps done reading V buffer
        if (it < 3)
            stage_v<G, R, OFF, HMIN, PB>(Vb, v, b, blockBase + (it + 1) * 16, tid);
        __pipeline_commit();
    }

    // Reduce the 8 warp slices in double, one global double atomic per element.
    for (int i = tid; i < G * 64; i += 256) {
        double tot = 0.0;
        #pragma unroll
        for (int ws = 0; ws < 8; ws++) tot += (double)sblk[ws * (G * 64) + i];
        atomicAdd(&g_sums[SUMBASE + b * (G * 64) + i], tot);
    }
}

// Fused pass 1: blocks [0,512): g0, [512,768): g1, [768,896): g2.
__global__ void __launch_bounds__(256) pass1_fused_kernel(
    const float* __restrict__ q,
    const float* __restrict__ k,
    const float* __restrict__ v)
{
    extern __shared__ float sm[];
    const int bx = blockIdx.x;
    if (bx < 512) {
        pass1_body<6, 1, 0, 0, 8192, X0_BASE, S0_BASE>(bx, sm, q, k, v);
    } else if (bx < 768) {
        pass1_body<5, 2, 1, 5, 4096, X1_BASE, S1_BASE>(bx - 512, sm, q, k, v);
    } else {
        pass1_body<5, 4, 2, 10, 2048, X2_BASE, S2_BASE>(bx - 768, sm, q, k, v);
    }
}

__device__ __forceinline__ float4 xload(int xoff, float4 rv)
{
    const uint2 raw = *reinterpret_cast<const uint2*>(g_xh + xoff);
    const __half2 h01 = *reinterpret_cast<const __half2*>(&raw.x);
    const __half2 h23 = *reinterpret_cast<const __half2*>(&raw.y);
    const float2 f01 = __half22float2(h01);
    const float2 f23 = __half22float2(h23);
    return make_float4(f01.x * rv.x, f01.y * rv.y, f23.x * rv.z, f23.y * rv.w);
}

// Pass 2: each thread writes four float4s at positions ph + {0,2048,4096,6144}
// (stride 2048 preserves parity -> identical group predicates, shared rsums).
// t layout: d4 (16) | h (16) | ph (2048) | b (4)  -> 2,097,152 threads.
// Also re-zeroes g_sums (already consumed by rsums_kernel) for next launch.
__global__ void __launch_bounds__(256) pass2_kernel(float* __restrict__ out)
{
    const int t = blockIdx.x * 256 + threadIdx.x;
    if (t < S_TOTAL) g_sums[t] = 0.0;

    const int d4 = t & 15;
    const int h  = (t >> 4) & 15;
    const int ph = (t >> 8) & 2047;     // p_i = ph + i*2048, i in 0..3
    const int b  = t >> 19;

    float4 v0 = make_float4(0.f, 0.f, 0.f, 0.f);
    float4 v1 = v0, v2 = v0, v3 = v0;

    if (h < 6) { // group 0: all positions
        const float4 rv = *reinterpret_cast<const float4*>(
            g_rsums + S0_BASE + (((b * 6 + h) << 6) + (d4 << 2)));
        const int j0 = b * 8192 + ph;           // j stride per output = 2048
        const int e  = (d4 << 2);
        v0 = xload(X0_BASE + (((j0        ) * 6 + h) << 6) + e, rv);
        v1 = xload(X0_BASE + (((j0 + 2048) * 6 + h) << 6) + e, rv);
        v2 = xload(X0_BASE + (((j0 + 4096) * 6 + h) << 6) + e, rv);
        v3 = xload(X0_BASE + (((j0 + 6144) * 6 + h) << 6) + e, rv);
    }
    if (h >= 5 && h < 10 && (ph & 1) == 1) { // group 1: odd positions
        const int hh = h - 5;
        const float4 rv = *reinterpret_cast<const float4*>(
            g_rsums + S1_BASE + (((b * 5 + hh) << 6) + (d4 << 2)));
        const int j0 = b * 4096 + (ph >> 1);    // j stride per output = 1024
        const int e  = (d4 << 2);
        const float4 t0 = xload(X1_BASE + (((j0        ) * 5 + hh) << 6) + e, rv);
        const float4 t1 = xload(X1_BASE + (((j0 + 1024) * 5 + hh) << 6) + e, rv);
        const float4 t2 = xload(X1_BASE + (((j0 + 2048) * 5 + hh) << 6) + e, rv);
        const float4 t3 = xload(X1_BASE + (((j0 + 3072) * 5 + hh) << 6) + e, rv);
        v0.x += t0.x; v0.y += t0.y; v0.z += t0.z; v0.w += t0.w;
        v1.x += t1.x; v1.y += t1.y; v1.z += t1.z; v1.w += t1.w;
        v2.x += t2.x; v2.y += t2.y; v2.z += t2.z; v2.w += t2.w;
        v3.x += t3.x; v3.y += t3.y; v3.z += t3.z; v3.w += t3.w;
    }
    if (h >= 10 && h < 15 && (ph & 3) == 2) { // group 2: pos%4==2
        const int hh = h - 10;
        const float4 rv = *reinterpret_cast<const float4*>(
            g_rsums + S2_BASE + (((b * 5 + hh) << 6) + (d4 << 2)));
        const int j0 = b * 2048 + (ph >> 2);    // j stride per output = 512
        const int e  = (d4 << 2);
        const float4 t0 = xload(X2_BASE + (((j0       ) * 5 + hh) << 6) + e, rv);
        const float4 t1 = xload(X2_BASE + (((j0 +  512) * 5 + hh) << 6) + e, rv);
        const float4 t2 = xload(X2_BASE + (((j0 + 1024) * 5 + hh) << 6) + e, rv);
        const float4 t3 = xload(X2_BASE + (((j0 + 1536) * 5 + hh) << 6) + e, rv);
        v0.x += t0.x; v0.y += t0.y; v0.z += t0.z; v0.w += t0.w;
        v1.x += t1.x; v1.y += t1.y; v1.z += t1.z; v1.w += t1.w;
        v2.x += t2.x; v2.y += t2.y; v2.z += t2.z; v2.w += t2.w;
        v3.x += t3.x; v3.y += t3.y; v3.z += t3.z; v3.w += t3.w;
    }

    const int o0 = (b * 8192 + ph) * 256 + h * 16 + d4;  // float4 index
    const int ostride = 2048 * 256;
    float4* o = reinterpret_cast<float4*>(out);
    o[o0]               = v0;
    o[o0 + ostride]     = v1;
    o[o0 + 2 * ostride] = v2;
    o[o0 + 3 * ostride] = v3;
}

extern "C" void kernel_launch(void* const* d_in, const int* in_sizes, int n_in,
                              void* d_out, int out_size)
{
    const float* q = (const float*)d_in[0];
    const float* k = (const float*)d_in[1];
    const float* v = (const float*)d_in[2];
    float* out = (float*)d_out;

    // Allow >48KB dynamic smem (idempotent; host-side, capture-safe).
    cudaFuncSetAttribute(pass1_fused_kernel,
                         cudaFuncAttributeMaxDynamicSharedMemorySize, SMEM_BYTES);

    // Pass 1: 512 (g0) + 256 (g1) + 128 (g2) blocks, 64 positions each.
    // g_sums starts zeroed (static init; re-zeroed by pass2 each launch).
    pass1_fused_kernel<<<896, 256, SMEM_BYTES>>>(q, k, v);

    rsums_kernel<<<16, 256>>>();

    // 2,097,152 threads, 4 float4 outputs each.
    pass2_kernel<<<8192, 256>>>(out);
}